// round 8
// baseline (speedup 1.0000x reference)
#include <cuda_runtime.h>
#include <cuda_fp16.h>

#define NMAX 100000
#define EMAX 3200000
#define F 64
#define GMAX 64
#define PAD 128        // bucket capacity per node (max realistic degree ~60)
#define PADSH 7

struct __align__(8) EdgeT { int s; __half2 w2; };   // weight pre-duplicated

// Scratch (device globals — no allocation allowed)
__device__ int   g_cnt_n[NMAX];                      // per-node fill cursor == degree
__device__ EdgeT g_csr[NMAX * PAD];                  // padded buckets {src, (w,w)}
__device__ __align__(16) __half g_hf[NMAX * F];      // fp16 feature table
__device__ __align__(16) float  g_x[NMAX * F];       // gather out / GEMM in
__device__ __align__(16) float  g_h2[NMAX * F];      // layer-2 activations
__device__ __align__(16) float  g_pool[GMAX * F];
__device__ float g_cnt[GMAX];

// ---------------------------------------------------------------------------
__global__ void k_zero(int n, int g) {
    int stride = gridDim.x * blockDim.x;
    for (int i = blockIdx.x * blockDim.x + threadIdx.x; i < n; i += stride) {
        g_cnt_n[i] = 0;
        if (i < g * F) g_pool[i] = 0.f;
        if (i < g) g_cnt[i] = 0.f;
    }
}

// ---------------------------------------------------------------------------
// fp32 -> fp16 table conversion
// ---------------------------------------------------------------------------
__global__ void k_cvt(const float* __restrict__ in, int total4) {
    int i = blockIdx.x * blockDim.x + threadIdx.x;
    if (i < total4) {
        float4 v = reinterpret_cast<const float4*>(in)[i];
        __half2 lo = __floats2half2_rn(v.x, v.y);
        __half2 hi = __floats2half2_rn(v.z, v.w);
        uint2 pk;
        pk.x = *reinterpret_cast<unsigned*>(&lo);
        pk.y = *reinterpret_cast<unsigned*>(&hi);
        reinterpret_cast<uint2*>(g_hf)[i] = pk;
    }
}

// ---------------------------------------------------------------------------
// Bucket fill: 4 edges per thread; weight stored as duplicated half2.
// Cursor atomic doubles as the degree histogram.
// ---------------------------------------------------------------------------
__global__ void k_fill(const float* __restrict__ ew, const int* __restrict__ src,
                       const int* __restrict__ dst, int e4) {
    int i = blockIdx.x * blockDim.x + threadIdx.x;
    if (i >= e4) return;
    int4   s = reinterpret_cast<const int4*>(src)[i];
    int4   d = reinterpret_cast<const int4*>(dst)[i];
    float4 w = reinterpret_cast<const float4*>(ew)[i];

    int p0 = atomicAdd(&g_cnt_n[d.x], 1);
    int p1 = atomicAdd(&g_cnt_n[d.y], 1);
    int p2 = atomicAdd(&g_cnt_n[d.z], 1);
    int p3 = atomicAdd(&g_cnt_n[d.w], 1);

    EdgeT r0; r0.s = s.x; r0.w2 = __float2half2_rn(w.x);
    EdgeT r1; r1.s = s.y; r1.w2 = __float2half2_rn(w.y);
    EdgeT r2; r2.s = s.z; r2.w2 = __float2half2_rn(w.z);
    EdgeT r3; r3.s = s.w; r3.w2 = __float2half2_rn(w.w);
    g_csr[(d.x << PADSH) + p0] = r0;
    g_csr[(d.y << PADSH) + p1] = r1;
    g_csr[(d.z << PADSH) + p2] = r2;
    g_csr[(d.w << PADSH) + p3] = r3;
}

// tail edges (e not divisible by 4)
__global__ void k_fill_tail(const float* __restrict__ ew, const int* __restrict__ src,
                            const int* __restrict__ dst, int lo, int e) {
    int i = lo + blockIdx.x * blockDim.x + threadIdx.x;
    if (i < e) {
        int d = dst[i];
        int pos = atomicAdd(&g_cnt_n[d], 1);
        EdgeT rec;
        rec.s = src[i];
        rec.w2 = __float2half2_rn(ew[i]);
        g_csr[(d << PADSH) + pos] = rec;
    }
}

// ---------------------------------------------------------------------------
// Gather: warp per dst node. HFMA2 accumulation with fp32 flush every 8 edges.
//   x[node] = ( (sum_e w*h[src_e]) / (sum_e w) + h[node] ) / (deg + 1)
// ---------------------------------------------------------------------------
__global__ void __launch_bounds__(256) k_gather(int n) {
    int w = (blockIdx.x * blockDim.x + threadIdx.x) >> 5;
    int l = threadIdx.x & 31;
    if (w >= n) return;

    int cnt = g_cnt_n[w];
    const EdgeT* row = g_csr + (w << PADSH);
    const __half2* hh = reinterpret_cast<const __half2*>(g_hf);

    float a0 = 0.f, a1 = 0.f, sw = 0.f;
    const __half2 z2 = __float2half2_rn(0.f);

    int e = 0;
    for (; e + 8 <= cnt; e += 8) {
        EdgeT ed[8];
        #pragma unroll
        for (int j = 0; j < 8; j++) ed[j] = row[e + j];
        __half2 v[8];
        #pragma unroll
        for (int j = 0; j < 8; j++) v[j] = hh[ed[j].s * 32 + l];

        __half2 acc = z2, swa = z2;
        #pragma unroll
        for (int j = 0; j < 8; j++) {
            acc = __hfma2(ed[j].w2, v[j], acc);
            swa = __hadd2(swa, ed[j].w2);
        }
        float2 f = __half22float2(acc);
        a0 += f.x; a1 += f.y;
        sw += __low2float(swa);
    }
    if (e < cnt) {
        __half2 acc = z2, swa = z2;
        for (; e < cnt; e++) {
            EdgeT ed = row[e];
            __half2 v = hh[ed.s * 32 + l];
            acc = __hfma2(ed.w2, v, acc);
            swa = __hadd2(swa, ed.w2);
        }
        float2 f = __half22float2(acc);
        a0 += f.x; a1 += f.y;
        sw += __low2float(swa);
    }

    float invsw = (cnt > 0) ? (1.0f / sw) : 0.f;
    float inv = 1.0f / ((float)cnt + 1.0f);
    float2 hs = __half22float2(hh[w * 32 + l]);
    float2 xo;
    xo.x = fmaf(a0, invsw, hs.x) * inv;
    xo.y = fmaf(a1, invsw, hs.y) * inv;
    reinterpret_cast<float2*>(g_x)[w * 32 + l] = xo;
}

// ---------------------------------------------------------------------------
// Register-tiled GEMM: out = relu(x @ W + b). 64x64 tile, 128 threads.
// ---------------------------------------------------------------------------
template <bool OUT_HALF>
__global__ void __launch_bounds__(128) k_gemm(const float* __restrict__ x,
                                              const float* __restrict__ W,
                                              const float* __restrict__ b,
                                              float* __restrict__ out, int n) {
    __shared__ float xsT[F][F + 1];
    __shared__ float Ws[F][F];
    __shared__ float bs[F];

    int t = threadIdx.x;
    for (int i = t; i < F * F; i += 128) Ws[i >> 6][i & 63] = W[i];
    if (t < F) bs[t] = b[t];

    int base = blockIdx.x * 64;

    #pragma unroll
    for (int j = 0; j < 8; j++) {
        int f = t + 128 * j;
        int nl = f >> 4;
        int k4 = f & 15;
        int gn = base + nl;
        float4 v = make_float4(0.f, 0.f, 0.f, 0.f);
        if (gn < n) v = reinterpret_cast<const float4*>(x)[gn * 16 + k4];
        xsT[k4 * 4 + 0][nl] = v.x;
        xsT[k4 * 4 + 1][nl] = v.y;
        xsT[k4 * 4 + 2][nl] = v.z;
        xsT[k4 * 4 + 3][nl] = v.w;
    }
    __syncthreads();

    int ng = t & 15;
    int cg = t >> 4;

    float acc[4][8];
    #pragma unroll
    for (int i = 0; i < 4; i++)
        #pragma unroll
        for (int j = 0; j < 8; j++) acc[i][j] = bs[cg * 8 + j];

    #pragma unroll 8
    for (int k = 0; k < F; k++) {
        float xf[4];
        #pragma unroll
        for (int i = 0; i < 4; i++) xf[i] = xsT[k][ng * 4 + i];
        float4 wa = *reinterpret_cast<float4*>(&Ws[k][cg * 8]);
        float4 wb = *reinterpret_cast<float4*>(&Ws[k][cg * 8 + 4]);
        #pragma unroll
        for (int i = 0; i < 4; i++) {
            acc[i][0] = fmaf(xf[i], wa.x, acc[i][0]);
            acc[i][1] = fmaf(xf[i], wa.y, acc[i][1]);
            acc[i][2] = fmaf(xf[i], wa.z, acc[i][2]);
            acc[i][3] = fmaf(xf[i], wa.w, acc[i][3]);
            acc[i][4] = fmaf(xf[i], wb.x, acc[i][4]);
            acc[i][5] = fmaf(xf[i], wb.y, acc[i][5]);
            acc[i][6] = fmaf(xf[i], wb.z, acc[i][6]);
            acc[i][7] = fmaf(xf[i], wb.w, acc[i][7]);
        }
    }

    #pragma unroll
    for (int i = 0; i < 4; i++) {
        int gn = base + ng * 4 + i;
        if (gn >= n) continue;
        if (OUT_HALF) {
            __half2 h0 = __floats2half2_rn(fmaxf(acc[i][0], 0.f), fmaxf(acc[i][1], 0.f));
            __half2 h1 = __floats2half2_rn(fmaxf(acc[i][2], 0.f), fmaxf(acc[i][3], 0.f));
            __half2 h2 = __floats2half2_rn(fmaxf(acc[i][4], 0.f), fmaxf(acc[i][5], 0.f));
            __half2 h3 = __floats2half2_rn(fmaxf(acc[i][6], 0.f), fmaxf(acc[i][7], 0.f));
            uint4 pk;
            pk.x = *reinterpret_cast<unsigned*>(&h0);
            pk.y = *reinterpret_cast<unsigned*>(&h1);
            pk.z = *reinterpret_cast<unsigned*>(&h2);
            pk.w = *reinterpret_cast<unsigned*>(&h3);
            reinterpret_cast<uint4*>(g_hf)[gn * 8 + cg] = pk;
        } else {
            float4 o0, o1;
            o0.x = fmaxf(acc[i][0], 0.f); o0.y = fmaxf(acc[i][1], 0.f);
            o0.z = fmaxf(acc[i][2], 0.f); o0.w = fmaxf(acc[i][3], 0.f);
            o1.x = fmaxf(acc[i][4], 0.f); o1.y = fmaxf(acc[i][5], 0.f);
            o1.z = fmaxf(acc[i][6], 0.f); o1.w = fmaxf(acc[i][7], 0.f);
            reinterpret_cast<float4*>(out)[gn * 16 + cg * 2]     = o0;
            reinterpret_cast<float4*>(out)[gn * 16 + cg * 2 + 1] = o1;
        }
    }
}

// ---------------------------------------------------------------------------
// Graph pooling: graph_ids sorted -> register run accumulation per warp
// ---------------------------------------------------------------------------
__global__ void k_pool(const float* __restrict__ h, const int* __restrict__ gid, int n) {
    int wid = (blockIdx.x * blockDim.x + threadIdx.x) >> 5;
    int lane = threadIdx.x & 31;
    int nwarps = (gridDim.x * blockDim.x) >> 5;
    int chunk = (n + nwarps - 1) / nwarps;
    int start = wid * chunk;
    int end = min(start + chunk, n);
    if (start >= end) return;

    int cur = -1;
    float s0 = 0.f, s1 = 0.f, c = 0.f;
    for (int node = start; node < end; node++) {
        int g = gid[node];
        if (g != cur) {
            if (cur >= 0) {
                atomicAdd(&g_pool[cur * F + lane], s0);
                atomicAdd(&g_pool[cur * F + lane + 32], s1);
                if (lane == 0) atomicAdd(&g_cnt[cur], c);
            }
            cur = g; s0 = s1 = 0.f; c = 0.f;
        }
        s0 += h[node * F + lane];
        s1 += h[node * F + lane + 32];
        c += 1.f;
    }
    if (cur >= 0) {
        atomicAdd(&g_pool[cur * F + lane], s0);
        atomicAdd(&g_pool[cur * F + lane + 32], s1);
        if (lane == 0) atomicAdd(&g_cnt[cur], c);
    }
}

// ---------------------------------------------------------------------------
__global__ void k_final(const float* __restrict__ Wc, const float* __restrict__ bc,
                        float* __restrict__ out, int g) {
    int t = threadIdx.x;
    if (t >= g * 2) return;
    int gi = t >> 1;
    int c = t & 1;
    float inv = 1.0f / fmaxf(g_cnt[gi], 1.0f);
    float s = bc[c];
    #pragma unroll
    for (int f = 0; f < F; f++)
        s = fmaf(g_pool[gi * F + f] * inv, Wc[f * 2 + c], s);
    out[t] = s;
}

// ---------------------------------------------------------------------------
extern "C" void kernel_launch(void* const* d_in, const int* in_sizes, int n_in,
                              void* d_out, int out_size) {
    const float* in_feat = (const float*)d_in[0];
    const float* ew      = (const float*)d_in[1];
    const float* W1      = (const float*)d_in[2];
    const float* b1      = (const float*)d_in[3];
    const float* W2      = (const float*)d_in[4];
    const float* b2      = (const float*)d_in[5];
    const float* Wc      = (const float*)d_in[6];
    const float* bc      = (const float*)d_in[7];
    const int*   src     = (const int*)d_in[8];
    const int*   dst     = (const int*)d_in[9];
    const int*   gid     = (const int*)d_in[10];

    int n = in_sizes[0] / F;
    int e = in_sizes[1];
    int g = out_size / 2;

    void *p_x = nullptr, *p_h2 = nullptr;
    cudaGetSymbolAddress(&p_x, g_x);
    cudaGetSymbolAddress(&p_h2, g_h2);
    float* xbuf = (float*)p_x;
    float* h2 = (float*)p_h2;

    int e4 = e >> 2;
    int nwb = (n * 32 + 255) / 256;     // warp-per-node
    int tiles = (n + 63) / 64;

    // prologue: zero cursors, convert input, fill buckets
    k_zero<<<512, 256>>>(n, g);
    k_cvt<<<(n * 16 + 255) / 256, 256>>>(in_feat, n * 16);
    k_fill<<<(e4 + 255) / 256, 256>>>(ew, src, dst, e4);
    if (e & 3)
        k_fill_tail<<<1, 256>>>(ew, src, dst, e4 * 4, e);

    // layer 1 (fp16 table = in_feat; GEMM writes fp16 h1 back into g_hf)
    k_gather<<<nwb, 256>>>(n);
    k_gemm<true><<<tiles, 128>>>(xbuf, W1, b1, nullptr, n);
    // layer 2 (fp16 table = h1; GEMM writes fp32 h2)
    k_gather<<<nwb, 256>>>(n);
    k_gemm<false><<<tiles, 128>>>(xbuf, W2, b2, h2, n);

    // pooling + classifier
    k_pool<<<512, 256>>>(h2, gid, n);
    k_final<<<1, 128>>>(Wc, bc, (float*)d_out, g);
}

// round 9
// speedup vs baseline: 1.0399x; 1.0399x over previous
#include <cuda_runtime.h>
#include <cuda_fp16.h>

#define NMAX 100000
#define EMAX 3200000
#define F 64
#define GMAX 64
#define PAD 128        // bucket capacity per node (max realistic degree ~60)
#define PADSH 7

struct __align__(8) EdgeT { int s; float w; };

// Scratch (device globals — no allocation allowed)
__device__ int   g_cnt_n[NMAX];                      // per-node fill cursor == degree
__device__ EdgeT g_csr[NMAX * PAD];                  // padded buckets {src, w}
__device__ __align__(16) __half g_hf[NMAX * F];      // fp16 feature table
__device__ __align__(16) float  g_x[NMAX * F];       // gather out / GEMM in
__device__ __align__(16) float  g_h2[NMAX * F];      // layer-2 activations
__device__ __align__(16) float  g_pool[GMAX * F];
__device__ float g_cnt[GMAX];

// ---------------------------------------------------------------------------
__global__ void k_zero(int n, int g) {
    int stride = gridDim.x * blockDim.x;
    for (int i = blockIdx.x * blockDim.x + threadIdx.x; i < n; i += stride) {
        g_cnt_n[i] = 0;
        if (i < g * F) g_pool[i] = 0.f;
        if (i < g) g_cnt[i] = 0.f;
    }
}

// ---------------------------------------------------------------------------
// fp32 -> fp16 table conversion
// ---------------------------------------------------------------------------
__global__ void k_cvt(const float* __restrict__ in, int total4) {
    int i = blockIdx.x * blockDim.x + threadIdx.x;
    if (i < total4) {
        float4 v = reinterpret_cast<const float4*>(in)[i];
        __half2 lo = __floats2half2_rn(v.x, v.y);
        __half2 hi = __floats2half2_rn(v.z, v.w);
        uint2 pk;
        pk.x = *reinterpret_cast<unsigned*>(&lo);
        pk.y = *reinterpret_cast<unsigned*>(&hi);
        reinterpret_cast<uint2*>(g_hf)[i] = pk;
    }
}

// ---------------------------------------------------------------------------
// Bucket fill: 4 edges per thread. Cursor atomic doubles as degree count.
// ---------------------------------------------------------------------------
__global__ void k_fill(const float* __restrict__ ew, const int* __restrict__ src,
                       const int* __restrict__ dst, int e4) {
    int i = blockIdx.x * blockDim.x + threadIdx.x;
    if (i >= e4) return;
    int4   s = reinterpret_cast<const int4*>(src)[i];
    int4   d = reinterpret_cast<const int4*>(dst)[i];
    float4 w = reinterpret_cast<const float4*>(ew)[i];

    int p0 = atomicAdd(&g_cnt_n[d.x], 1);
    int p1 = atomicAdd(&g_cnt_n[d.y], 1);
    int p2 = atomicAdd(&g_cnt_n[d.z], 1);
    int p3 = atomicAdd(&g_cnt_n[d.w], 1);

    EdgeT r0; r0.s = s.x; r0.w = w.x;
    EdgeT r1; r1.s = s.y; r1.w = w.y;
    EdgeT r2; r2.s = s.z; r2.w = w.z;
    EdgeT r3; r3.s = s.w; r3.w = w.w;
    g_csr[(d.x << PADSH) + p0] = r0;
    g_csr[(d.y << PADSH) + p1] = r1;
    g_csr[(d.z << PADSH) + p2] = r2;
    g_csr[(d.w << PADSH) + p3] = r3;
}

// tail edges (e not divisible by 4)
__global__ void k_fill_tail(const float* __restrict__ ew, const int* __restrict__ src,
                            const int* __restrict__ dst, int lo, int e) {
    int i = lo + blockIdx.x * blockDim.x + threadIdx.x;
    if (i < e) {
        int d = dst[i];
        int pos = atomicAdd(&g_cnt_n[d], 1);
        EdgeT rec;
        rec.s = src[i];
        rec.w = ew[i];
        g_csr[(d << PADSH) + pos] = rec;
    }
}

// ---------------------------------------------------------------------------
// Normalize pass (once, shared by both layers): rewrite each stored weight as
//   w' = w / (sum_row(w) * (deg + 1))
// so the gather needs no per-edge weight-sum and no epilogue normalization.
// Warp per node.
// ---------------------------------------------------------------------------
__global__ void __launch_bounds__(256) k_norm(int n) {
    int w = (blockIdx.x * blockDim.x + threadIdx.x) >> 5;
    int l = threadIdx.x & 31;
    if (w >= n) return;

    int cnt = g_cnt_n[w];
    EdgeT* row = g_csr + (w << PADSH);

    float s = 0.f;
    for (int e = l; e < cnt; e += 32) s += row[e].w;
    #pragma unroll
    for (int d = 16; d; d >>= 1) s += __shfl_xor_sync(0xffffffffu, s, d);

    if (cnt > 0) {
        float scale = 1.0f / (s * (float)(cnt + 1));
        for (int e = l; e < cnt; e += 32) row[e].w *= scale;
    }
}

// ---------------------------------------------------------------------------
// Gather: warp per dst node, fp16 table, fp32 accumulate, pre-normalized w.
//   x[node] = sum_e w'_e * h[src_e]  +  h[node] / (deg + 1)
// ---------------------------------------------------------------------------
__global__ void __launch_bounds__(256) k_gather(int n) {
    int w = (blockIdx.x * blockDim.x + threadIdx.x) >> 5;
    int l = threadIdx.x & 31;
    if (w >= n) return;

    int cnt = g_cnt_n[w];
    const EdgeT* row = g_csr + (w << PADSH);
    const __half2* hh = reinterpret_cast<const __half2*>(g_hf) + l;

    float a0 = 0.f, a1 = 0.f;

    int e = 0;
    for (; e + 8 <= cnt; e += 8) {
        EdgeT ed[8];
        #pragma unroll
        for (int j = 0; j < 8; j++) ed[j] = row[e + j];
        float2 v[8];
        #pragma unroll
        for (int j = 0; j < 8; j++) v[j] = __half22float2(hh[ed[j].s * 32]);
        #pragma unroll
        for (int j = 0; j < 8; j++) {
            a0 = fmaf(ed[j].w, v[j].x, a0);
            a1 = fmaf(ed[j].w, v[j].y, a1);
        }
    }
    for (; e < cnt; e++) {
        EdgeT ed = row[e];
        float2 v = __half22float2(hh[ed.s * 32]);
        a0 = fmaf(ed.w, v.x, a0);
        a1 = fmaf(ed.w, v.y, a1);
    }

    float inv = 1.0f / ((float)cnt + 1.0f);
    float2 hs = __half22float2(hh[w * 32]);
    float2 xo;
    xo.x = fmaf(hs.x, inv, a0);
    xo.y = fmaf(hs.y, inv, a1);
    reinterpret_cast<float2*>(g_x)[w * 32 + l] = xo;
}

// ---------------------------------------------------------------------------
// Register-tiled GEMM: out = relu(x @ W + b). 64x64 tile, 128 threads.
// ---------------------------------------------------------------------------
template <bool OUT_HALF>
__global__ void __launch_bounds__(128) k_gemm(const float* __restrict__ x,
                                              const float* __restrict__ W,
                                              const float* __restrict__ b,
                                              float* __restrict__ out, int n) {
    __shared__ float xsT[F][F + 1];
    __shared__ float Ws[F][F];
    __shared__ float bs[F];

    int t = threadIdx.x;
    for (int i = t; i < F * F; i += 128) Ws[i >> 6][i & 63] = W[i];
    if (t < F) bs[t] = b[t];

    int base = blockIdx.x * 64;

    #pragma unroll
    for (int j = 0; j < 8; j++) {
        int f = t + 128 * j;
        int nl = f >> 4;
        int k4 = f & 15;
        int gn = base + nl;
        float4 v = make_float4(0.f, 0.f, 0.f, 0.f);
        if (gn < n) v = reinterpret_cast<const float4*>(x)[gn * 16 + k4];
        xsT[k4 * 4 + 0][nl] = v.x;
        xsT[k4 * 4 + 1][nl] = v.y;
        xsT[k4 * 4 + 2][nl] = v.z;
        xsT[k4 * 4 + 3][nl] = v.w;
    }
    __syncthreads();

    int ng = t & 15;
    int cg = t >> 4;

    float acc[4][8];
    #pragma unroll
    for (int i = 0; i < 4; i++)
        #pragma unroll
        for (int j = 0; j < 8; j++) acc[i][j] = bs[cg * 8 + j];

    #pragma unroll 8
    for (int k = 0; k < F; k++) {
        float xf[4];
        #pragma unroll
        for (int i = 0; i < 4; i++) xf[i] = xsT[k][ng * 4 + i];
        float4 wa = *reinterpret_cast<float4*>(&Ws[k][cg * 8]);
        float4 wb = *reinterpret_cast<float4*>(&Ws[k][cg * 8 + 4]);
        #pragma unroll
        for (int i = 0; i < 4; i++) {
            acc[i][0] = fmaf(xf[i], wa.x, acc[i][0]);
            acc[i][1] = fmaf(xf[i], wa.y, acc[i][1]);
            acc[i][2] = fmaf(xf[i], wa.z, acc[i][2]);
            acc[i][3] = fmaf(xf[i], wa.w, acc[i][3]);
            acc[i][4] = fmaf(xf[i], wb.x, acc[i][4]);
            acc[i][5] = fmaf(xf[i], wb.y, acc[i][5]);
            acc[i][6] = fmaf(xf[i], wb.z, acc[i][6]);
            acc[i][7] = fmaf(xf[i], wb.w, acc[i][7]);
        }
    }

    #pragma unroll
    for (int i = 0; i < 4; i++) {
        int gn = base + ng * 4 + i;
        if (gn >= n) continue;
        if (OUT_HALF) {
            __half2 h0 = __floats2half2_rn(fmaxf(acc[i][0], 0.f), fmaxf(acc[i][1], 0.f));
            __half2 h1 = __floats2half2_rn(fmaxf(acc[i][2], 0.f), fmaxf(acc[i][3], 0.f));
            __half2 h2 = __floats2half2_rn(fmaxf(acc[i][4], 0.f), fmaxf(acc[i][5], 0.f));
            __half2 h3 = __floats2half2_rn(fmaxf(acc[i][6], 0.f), fmaxf(acc[i][7], 0.f));
            uint4 pk;
            pk.x = *reinterpret_cast<unsigned*>(&h0);
            pk.y = *reinterpret_cast<unsigned*>(&h1);
            pk.z = *reinterpret_cast<unsigned*>(&h2);
            pk.w = *reinterpret_cast<unsigned*>(&h3);
            reinterpret_cast<uint4*>(g_hf)[gn * 8 + cg] = pk;
        } else {
            float4 o0, o1;
            o0.x = fmaxf(acc[i][0], 0.f); o0.y = fmaxf(acc[i][1], 0.f);
            o0.z = fmaxf(acc[i][2], 0.f); o0.w = fmaxf(acc[i][3], 0.f);
            o1.x = fmaxf(acc[i][4], 0.f); o1.y = fmaxf(acc[i][5], 0.f);
            o1.z = fmaxf(acc[i][6], 0.f); o1.w = fmaxf(acc[i][7], 0.f);
            reinterpret_cast<float4*>(out)[gn * 16 + cg * 2]     = o0;
            reinterpret_cast<float4*>(out)[gn * 16 + cg * 2 + 1] = o1;
        }
    }
}

// ---------------------------------------------------------------------------
// Graph pooling: graph_ids sorted -> register run accumulation per warp
// ---------------------------------------------------------------------------
__global__ void k_pool(const float* __restrict__ h, const int* __restrict__ gid, int n) {
    int wid = (blockIdx.x * blockDim.x + threadIdx.x) >> 5;
    int lane = threadIdx.x & 31;
    int nwarps = (gridDim.x * blockDim.x) >> 5;
    int chunk = (n + nwarps - 1) / nwarps;
    int start = wid * chunk;
    int end = min(start + chunk, n);
    if (start >= end) return;

    int cur = -1;
    float s0 = 0.f, s1 = 0.f, c = 0.f;
    for (int node = start; node < end; node++) {
        int g = gid[node];
        if (g != cur) {
            if (cur >= 0) {
                atomicAdd(&g_pool[cur * F + lane], s0);
                atomicAdd(&g_pool[cur * F + lane + 32], s1);
                if (lane == 0) atomicAdd(&g_cnt[cur], c);
            }
            cur = g; s0 = s1 = 0.f; c = 0.f;
        }
        s0 += h[node * F + lane];
        s1 += h[node * F + lane + 32];
        c += 1.f;
    }
    if (cur >= 0) {
        atomicAdd(&g_pool[cur * F + lane], s0);
        atomicAdd(&g_pool[cur * F + lane + 32], s1);
        if (lane == 0) atomicAdd(&g_cnt[cur], c);
    }
}

// ---------------------------------------------------------------------------
__global__ void k_final(const float* __restrict__ Wc, const float* __restrict__ bc,
                        float* __restrict__ out, int g) {
    int t = threadIdx.x;
    if (t >= g * 2) return;
    int gi = t >> 1;
    int c = t & 1;
    float inv = 1.0f / fmaxf(g_cnt[gi], 1.0f);
    float s = bc[c];
    #pragma unroll
    for (int f = 0; f < F; f++)
        s = fmaf(g_pool[gi * F + f] * inv, Wc[f * 2 + c], s);
    out[t] = s;
}

// ---------------------------------------------------------------------------
extern "C" void kernel_launch(void* const* d_in, const int* in_sizes, int n_in,
                              void* d_out, int out_size) {
    const float* in_feat = (const float*)d_in[0];
    const float* ew      = (const float*)d_in[1];
    const float* W1      = (const float*)d_in[2];
    const float* b1      = (const float*)d_in[3];
    const float* W2      = (const float*)d_in[4];
    const float* b2      = (const float*)d_in[5];
    const float* Wc      = (const float*)d_in[6];
    const float* bc      = (const float*)d_in[7];
    const int*   src     = (const int*)d_in[8];
    const int*   dst     = (const int*)d_in[9];
    const int*   gid     = (const int*)d_in[10];

    int n = in_sizes[0] / F;
    int e = in_sizes[1];
    int g = out_size / 2;

    void *p_x = nullptr, *p_h2 = nullptr;
    cudaGetSymbolAddress(&p_x, g_x);
    cudaGetSymbolAddress(&p_h2, g_h2);
    float* xbuf = (float*)p_x;
    float* h2 = (float*)p_h2;

    int e4 = e >> 2;
    int nwb = (n * 32 + 255) / 256;     // warp-per-node
    int tiles = (n + 63) / 64;

    // prologue: zero cursors, convert input, fill buckets, normalize weights
    k_zero<<<512, 256>>>(n, g);
    k_cvt<<<(n * 16 + 255) / 256, 256>>>(in_feat, n * 16);
    k_fill<<<(e4 + 255) / 256, 256>>>(ew, src, dst, e4);
    if (e & 3)
        k_fill_tail<<<1, 256>>>(ew, src, dst, e4 * 4, e);
    k_norm<<<nwb, 256>>>(n);

    // layer 1 (fp16 table = in_feat; GEMM writes fp16 h1 back into g_hf)
    k_gather<<<nwb, 256>>>(n);
    k_gemm<true><<<tiles, 128>>>(xbuf, W1, b1, nullptr, n);
    // layer 2 (fp16 table = h1; GEMM writes fp32 h2)
    k_gather<<<nwb, 256>>>(n);
    k_gemm<false><<<tiles, 128>>>(xbuf, W2, b2, h2, n);

    // pooling + classifier
    k_pool<<<512, 256>>>(h2, gid, n);
    k_final<<<1, 128>>>(Wc, bc, (float*)d_out, g);
}

// round 10
// speedup vs baseline: 1.1291x; 1.0857x over previous
#include <cuda_runtime.h>
#include <cuda_fp16.h>

#define NMAX 100000
#define EMAX 3200000
#define F 64
#define GMAX 64
#define PAD 128        // bucket capacity per node (max realistic degree ~60)
#define PADSH 7

struct __align__(8) EdgeT { int s; float w; };

// Scratch (device globals — no allocation allowed)
__device__ int   g_cnt_n[NMAX];                      // per-node fill cursor == degree
__device__ float g_scale[NMAX];                      // 1/(sum_w * (deg+1)), layer-1 byproduct
__device__ __align__(16) EdgeT g_csr[NMAX * PAD];    // padded buckets {src, w}
__device__ __align__(16) __half g_hf[NMAX * F];      // fp16 feature table
__device__ __align__(16) float  g_x[NMAX * F];       // gather out / GEMM in
__device__ __align__(16) float  g_h2[NMAX * F];      // layer-2 activations
__device__ __align__(16) float  g_pool[GMAX * F];
__device__ float g_cnt[GMAX];

// ---------------------------------------------------------------------------
__global__ void k_zero(int n, int g) {
    int stride = gridDim.x * blockDim.x;
    for (int i = blockIdx.x * blockDim.x + threadIdx.x; i < n; i += stride) {
        g_cnt_n[i] = 0;
        if (i < g * F) g_pool[i] = 0.f;
        if (i < g) g_cnt[i] = 0.f;
    }
}

// ---------------------------------------------------------------------------
// fp32 -> fp16 table conversion
// ---------------------------------------------------------------------------
__global__ void k_cvt(const float* __restrict__ in, int total4) {
    int i = blockIdx.x * blockDim.x + threadIdx.x;
    if (i < total4) {
        float4 v = reinterpret_cast<const float4*>(in)[i];
        __half2 lo = __floats2half2_rn(v.x, v.y);
        __half2 hi = __floats2half2_rn(v.z, v.w);
        uint2 pk;
        pk.x = *reinterpret_cast<unsigned*>(&lo);
        pk.y = *reinterpret_cast<unsigned*>(&hi);
        reinterpret_cast<uint2*>(g_hf)[i] = pk;
    }
}

// ---------------------------------------------------------------------------
// Bucket fill: 4 edges per thread. Cursor atomic doubles as degree count.
// ---------------------------------------------------------------------------
__global__ void k_fill(const float* __restrict__ ew, const int* __restrict__ src,
                       const int* __restrict__ dst, int e4) {
    int i = blockIdx.x * blockDim.x + threadIdx.x;
    if (i >= e4) return;
    int4   s = reinterpret_cast<const int4*>(src)[i];
    int4   d = reinterpret_cast<const int4*>(dst)[i];
    float4 w = reinterpret_cast<const float4*>(ew)[i];

    int p0 = atomicAdd(&g_cnt_n[d.x], 1);
    int p1 = atomicAdd(&g_cnt_n[d.y], 1);
    int p2 = atomicAdd(&g_cnt_n[d.z], 1);
    int p3 = atomicAdd(&g_cnt_n[d.w], 1);

    EdgeT r0; r0.s = s.x; r0.w = w.x;
    EdgeT r1; r1.s = s.y; r1.w = w.y;
    EdgeT r2; r2.s = s.z; r2.w = w.z;
    EdgeT r3; r3.s = s.w; r3.w = w.w;
    g_csr[(d.x << PADSH) + p0] = r0;
    g_csr[(d.y << PADSH) + p1] = r1;
    g_csr[(d.z << PADSH) + p2] = r2;
    g_csr[(d.w << PADSH) + p3] = r3;
}

// tail edges (e not divisible by 4)
__global__ void k_fill_tail(const float* __restrict__ ew, const int* __restrict__ src,
                            const int* __restrict__ dst, int lo, int e) {
    int i = lo + blockIdx.x * blockDim.x + threadIdx.x;
    if (i < e) {
        int d = dst[i];
        int pos = atomicAdd(&g_cnt_n[d], 1);
        EdgeT rec;
        rec.s = src[i];
        rec.w = ew[i];
        g_csr[(d << PADSH) + pos] = rec;
    }
}

// ---------------------------------------------------------------------------
// Gather: warp per dst node, fp16 table, fp32 accumulate.
// Records loaded 2-at-a-time via uint4 (LDG.128).
// FIRST: also accumulate sum_w, store g_scale[node] = 1/(sum_w*(deg+1)).
// else:  load the precomputed scale (no per-edge weight-sum work).
//   x[node] = sc * sum_e w_e*h[src_e]  +  h[node] / (deg + 1)
// ---------------------------------------------------------------------------
template <bool FIRST>
__global__ void __launch_bounds__(256) k_gather(int n) {
    int w = (blockIdx.x * blockDim.x + threadIdx.x) >> 5;
    int l = threadIdx.x & 31;
    if (w >= n) return;

    int cnt = g_cnt_n[w];
    const EdgeT* row = g_csr + (w << PADSH);
    const uint4* row4 = reinterpret_cast<const uint4*>(row);
    const __half2* hh = reinterpret_cast<const __half2*>(g_hf) + l;

    float a0 = 0.f, a1 = 0.f, sw = 0.f;

    int e = 0;
    for (; e + 8 <= cnt; e += 8) {
        uint4 r[4];
        #pragma unroll
        for (int j = 0; j < 4; j++) r[j] = row4[(e >> 1) + j];
        float2 v[8];
        #pragma unroll
        for (int j = 0; j < 4; j++) {
            v[2 * j]     = __half22float2(hh[r[j].x * 32]);
            v[2 * j + 1] = __half22float2(hh[r[j].z * 32]);
        }
        #pragma unroll
        for (int j = 0; j < 4; j++) {
            float w0 = __int_as_float(r[j].y);
            float w1 = __int_as_float(r[j].w);
            a0 = fmaf(w0, v[2 * j].x, a0);
            a1 = fmaf(w0, v[2 * j].y, a1);
            a0 = fmaf(w1, v[2 * j + 1].x, a0);
            a1 = fmaf(w1, v[2 * j + 1].y, a1);
            if (FIRST) sw += w0 + w1;
        }
    }
    for (; e < cnt; e++) {
        EdgeT ed = row[e];
        float2 v = __half22float2(hh[ed.s * 32]);
        a0 = fmaf(ed.w, v.x, a0);
        a1 = fmaf(ed.w, v.y, a1);
        if (FIRST) sw += ed.w;
    }

    float inv = 1.0f / ((float)cnt + 1.0f);
    float sc;
    if (FIRST) {
        sc = (cnt > 0) ? (inv / sw) : 0.f;
        if (l == 0) g_scale[w] = sc;
    } else {
        sc = g_scale[w];
    }

    float2 hs = __half22float2(hh[w * 32]);
    float2 xo;
    xo.x = fmaf(a0, sc, hs.x * inv);
    xo.y = fmaf(a1, sc, hs.y * inv);
    reinterpret_cast<float2*>(g_x)[w * 32 + l] = xo;
}

// ---------------------------------------------------------------------------
// Register-tiled GEMM: out = relu(x @ W + b). 64x64 tile, 128 threads.
// ---------------------------------------------------------------------------
template <bool OUT_HALF>
__global__ void __launch_bounds__(128) k_gemm(const float* __restrict__ x,
                                              const float* __restrict__ W,
                                              const float* __restrict__ b,
                                              float* __restrict__ out, int n) {
    __shared__ float xsT[F][F + 1];
    __shared__ float Ws[F][F];
    __shared__ float bs[F];

    int t = threadIdx.x;
    for (int i = t; i < F * F; i += 128) Ws[i >> 6][i & 63] = W[i];
    if (t < F) bs[t] = b[t];

    int base = blockIdx.x * 64;

    #pragma unroll
    for (int j = 0; j < 8; j++) {
        int f = t + 128 * j;
        int nl = f >> 4;
        int k4 = f & 15;
        int gn = base + nl;
        float4 v = make_float4(0.f, 0.f, 0.f, 0.f);
        if (gn < n) v = reinterpret_cast<const float4*>(x)[gn * 16 + k4];
        xsT[k4 * 4 + 0][nl] = v.x;
        xsT[k4 * 4 + 1][nl] = v.y;
        xsT[k4 * 4 + 2][nl] = v.z;
        xsT[k4 * 4 + 3][nl] = v.w;
    }
    __syncthreads();

    int ng = t & 15;
    int cg = t >> 4;

    float acc[4][8];
    #pragma unroll
    for (int i = 0; i < 4; i++)
        #pragma unroll
        for (int j = 0; j < 8; j++) acc[i][j] = bs[cg * 8 + j];

    #pragma unroll 8
    for (int k = 0; k < F; k++) {
        float xf[4];
        #pragma unroll
        for (int i = 0; i < 4; i++) xf[i] = xsT[k][ng * 4 + i];
        float4 wa = *reinterpret_cast<float4*>(&Ws[k][cg * 8]);
        float4 wb = *reinterpret_cast<float4*>(&Ws[k][cg * 8 + 4]);
        #pragma unroll
        for (int i = 0; i < 4; i++) {
            acc[i][0] = fmaf(xf[i], wa.x, acc[i][0]);
            acc[i][1] = fmaf(xf[i], wa.y, acc[i][1]);
            acc[i][2] = fmaf(xf[i], wa.z, acc[i][2]);
            acc[i][3] = fmaf(xf[i], wa.w, acc[i][3]);
            acc[i][4] = fmaf(xf[i], wb.x, acc[i][4]);
            acc[i][5] = fmaf(xf[i], wb.y, acc[i][5]);
            acc[i][6] = fmaf(xf[i], wb.z, acc[i][6]);
            acc[i][7] = fmaf(xf[i], wb.w, acc[i][7]);
        }
    }

    #pragma unroll
    for (int i = 0; i < 4; i++) {
        int gn = base + ng * 4 + i;
        if (gn >= n) continue;
        if (OUT_HALF) {
            __half2 h0 = __floats2half2_rn(fmaxf(acc[i][0], 0.f), fmaxf(acc[i][1], 0.f));
            __half2 h1 = __floats2half2_rn(fmaxf(acc[i][2], 0.f), fmaxf(acc[i][3], 0.f));
            __half2 h2 = __floats2half2_rn(fmaxf(acc[i][4], 0.f), fmaxf(acc[i][5], 0.f));
            __half2 h3 = __floats2half2_rn(fmaxf(acc[i][6], 0.f), fmaxf(acc[i][7], 0.f));
            uint4 pk;
            pk.x = *reinterpret_cast<unsigned*>(&h0);
            pk.y = *reinterpret_cast<unsigned*>(&h1);
            pk.z = *reinterpret_cast<unsigned*>(&h2);
            pk.w = *reinterpret_cast<unsigned*>(&h3);
            reinterpret_cast<uint4*>(g_hf)[gn * 8 + cg] = pk;
        } else {
            float4 o0, o1;
            o0.x = fmaxf(acc[i][0], 0.f); o0.y = fmaxf(acc[i][1], 0.f);
            o0.z = fmaxf(acc[i][2], 0.f); o0.w = fmaxf(acc[i][3], 0.f);
            o1.x = fmaxf(acc[i][4], 0.f); o1.y = fmaxf(acc[i][5], 0.f);
            o1.z = fmaxf(acc[i][6], 0.f); o1.w = fmaxf(acc[i][7], 0.f);
            reinterpret_cast<float4*>(out)[gn * 16 + cg * 2]     = o0;
            reinterpret_cast<float4*>(out)[gn * 16 + cg * 2 + 1] = o1;
        }
    }
}

// ---------------------------------------------------------------------------
// Graph pooling: graph_ids sorted -> register run accumulation per warp
// ---------------------------------------------------------------------------
__global__ void k_pool(const float* __restrict__ h, const int* __restrict__ gid, int n) {
    int wid = (blockIdx.x * blockDim.x + threadIdx.x) >> 5;
    int lane = threadIdx.x & 31;
    int nwarps = (gridDim.x * blockDim.x) >> 5;
    int chunk = (n + nwarps - 1) / nwarps;
    int start = wid * chunk;
    int end = min(start + chunk, n);
    if (start >= end) return;

    int cur = -1;
    float s0 = 0.f, s1 = 0.f, c = 0.f;
    for (int node = start; node < end; node++) {
        int g = gid[node];
        if (g != cur) {
            if (cur >= 0) {
                atomicAdd(&g_pool[cur * F + lane], s0);
                atomicAdd(&g_pool[cur * F + lane + 32], s1);
                if (lane == 0) atomicAdd(&g_cnt[cur], c);
            }
            cur = g; s0 = s1 = 0.f; c = 0.f;
        }
        s0 += h[node * F + lane];
        s1 += h[node * F + lane + 32];
        c += 1.f;
    }
    if (cur >= 0) {
        atomicAdd(&g_pool[cur * F + lane], s0);
        atomicAdd(&g_pool[cur * F + lane + 32], s1);
        if (lane == 0) atomicAdd(&g_cnt[cur], c);
    }
}

// ---------------------------------------------------------------------------
__global__ void k_final(const float* __restrict__ Wc, const float* __restrict__ bc,
                        float* __restrict__ out, int g) {
    int t = threadIdx.x;
    if (t >= g * 2) return;
    int gi = t >> 1;
    int c = t & 1;
    float inv = 1.0f / fmaxf(g_cnt[gi], 1.0f);
    float s = bc[c];
    #pragma unroll
    for (int f = 0; f < F; f++)
        s = fmaf(g_pool[gi * F + f] * inv, Wc[f * 2 + c], s);
    out[t] = s;
}

// ---------------------------------------------------------------------------
extern "C" void kernel_launch(void* const* d_in, const int* in_sizes, int n_in,
                              void* d_out, int out_size) {
    const float* in_feat = (const float*)d_in[0];
    const float* ew      = (const float*)d_in[1];
    const float* W1      = (const float*)d_in[2];
    const float* b1      = (const float*)d_in[3];
    const float* W2      = (const float*)d_in[4];
    const float* b2      = (const float*)d_in[5];
    const float* Wc      = (const float*)d_in[6];
    const float* bc      = (const float*)d_in[7];
    const int*   src     = (const int*)d_in[8];
    const int*   dst     = (const int*)d_in[9];
    const int*   gid     = (const int*)d_in[10];

    int n = in_sizes[0] / F;
    int e = in_sizes[1];
    int g = out_size / 2;

    void *p_x = nullptr, *p_h2 = nullptr;
    cudaGetSymbolAddress(&p_x, g_x);
    cudaGetSymbolAddress(&p_h2, g_h2);
    float* xbuf = (float*)p_x;
    float* h2 = (float*)p_h2;

    int e4 = e >> 2;
    int nwb = (n * 32 + 255) / 256;     // warp-per-node
    int tiles = (n + 63) / 64;

    // prologue: zero cursors, convert input, fill buckets
    k_zero<<<512, 256>>>(n, g);
    k_cvt<<<(n * 16 + 255) / 256, 256>>>(in_feat, n * 16);
    k_fill<<<(e4 + 255) / 256, 256>>>(ew, src, dst, e4);
    if (e & 3)
        k_fill_tail<<<1, 256>>>(ew, src, dst, e4 * 4, e);

    // layer 1 (computes + stores per-node scale; GEMM writes fp16 h1 into g_hf)
    k_gather<true><<<nwb, 256>>>(n);
    k_gemm<true><<<tiles, 128>>>(xbuf, W1, b1, nullptr, n);
    // layer 2 (reuses stored scale; GEMM writes fp32 h2)
    k_gather<false><<<nwb, 256>>>(n);
    k_gemm<false><<<tiles, 128>>>(xbuf, W2, b2, h2, n);

    // pooling + classifier
    k_pool<<<512, 256>>>(h2, gid, n);
    k_final<<<1, 128>>>(Wc, bc, (float*)d_out, g);
}